// round 5
// baseline (speedup 1.0000x reference)
#include <cuda_runtime.h>

#define DIM    256
#define NBINS  32
#define NKNOTS 33
#define TPER   (NKNOTS * DIM)       // 8448 floats per table, layout [knot][dim]
#define TTOT   (3 * TPER)           // cw | ch | d
#define ROWS   8
#define GRID_MAIN 296               // 2 blocks/SM * 148 SMs

// Precomputed knot tables, layout [knot][dim] (bank = dim mod 32 -> conflict-free
// for any data-dependent knot index):
// [0,TPER) cumwidths, [TPER,2*TPER) cumheights, [2*TPER,3*TPER) derivatives.
__device__ float g_tab[TTOT];

__device__ __forceinline__ float softplus_f(float v) {
    return (v > 15.0f) ? v : log1pf(__expf(v));
}

// One warp per dim: softmax -> min-size floor -> inclusive scan -> knots.
__global__ void precompute_kernel(const float* __restrict__ width,
                                  const float* __restrict__ height,
                                  const float* __restrict__ deriv)
{
    int warp = (blockIdx.x * blockDim.x + threadIdx.x) >> 5;  // = dim
    int lane = threadIdx.x & 31;
    if (warp >= DIM) return;

    #pragma unroll
    for (int a = 0; a < 2; ++a) {
        const float* src = a ? height : width;
        float v = src[warp * NBINS + lane];

        float m = v;
        #pragma unroll
        for (int o = 16; o; o >>= 1) m = fmaxf(m, __shfl_xor_sync(0xffffffffu, m, o));
        float e = __expf(v - m);
        float s = e;
        #pragma unroll
        for (int o = 16; o; o >>= 1) s += __shfl_xor_sync(0xffffffffu, s, o);

        float size = 1e-3f + (1.0f - NBINS * 1e-3f) * (e / s);

        // inclusive warp scan (cumsum)
        float c = size;
        #pragma unroll
        for (int o = 1; o < 32; o <<= 1) {
            float n = __shfl_up_sync(0xffffffffu, c, o);
            if (lane >= o) c += n;
        }

        float* knots = g_tab + a * TPER;                           // [knot][dim]
        knots[(lane + 1) * DIM + warp] = (lane == 31) ? 1.0f : c;  // pin last to UPPER
        if (lane == 0) knots[warp] = 0.0f;                         // pin first to LOWER
    }

    {
        // derivatives: MIN_DERIVATIVE + softplus(pad(deriv, const));
        // boundary value: MIN_DERIVATIVE + softplus(log(expm1(1-MIN_DERIVATIVE))) = 1.0
        float* dd = g_tab + 2 * TPER;
        if (lane < NBINS - 1)
            dd[(lane + 1) * DIM + warp] = 1e-3f + softplus_f(deriv[warp * (NBINS - 1) + lane]);
        if (lane == 31) { dd[warp] = 1.0f; dd[NBINS * DIM + warp] = 1.0f; }
    }
}

template <bool CHK>
__device__ __forceinline__ void process_rows(
    const float* __restrict__ x, float* __restrict__ out,
    const float* __restrict__ cw, const float* __restrict__ chh,
    const float* __restrict__ dd,
    int r0, int B, int ldoff, int d)
{
    float xv[ROWS], xc[ROWS];
    #pragma unroll
    for (int j = 0; j < ROWS; ++j) {
        int r = r0 + j;
        xv[j] = (!CHK || r < B) ? x[r * DIM + d] : 0.5f;
    }
    #pragma unroll
    for (int j = 0; j < ROWS; ++j)
        xc[j] = fminf(fmaxf(xv[j], 0.0f), 1.0f);

    // Arithmetic guess + exact fixup. Knots are near-uniform (softmax of small
    // logits), so the loops statistically never iterate, but remain correct for
    // arbitrary knot spacing. (c0, c1) carry the bracketing knot values so the
    // evaluation phase needs no cw re-gather.
    int   bin[ROWS];
    float cw0[ROWS], cw1[ROWS];
    #pragma unroll
    for (int j = 0; j < ROWS; ++j) {
        int g = min((int)(xc[j] * (float)NBINS), NBINS - 1);
        float c0 = cw[g * DIM];
        float c1 = cw[(g + 1) * DIM];
        while (g > 0 && c0 > xc[j])              { --g; c1 = c0; c0 = cw[g * DIM]; }
        while (g < NBINS - 1 && c1 <= xc[j])     { ++g; c0 = c1; c1 = cw[(g + 1) * DIM]; }
        bin[j] = g; cw0[j] = c0; cw1[j] = c1;
    }

    #pragma unroll
    for (int j = 0; j < ROWS; ++j) {
        int   b   = bin[j] * DIM;
        float ch0 = chh[b], ch1 = chh[b + DIM];
        float d0  = dd[b],  d1  = dd[b + DIM];

        float w      = cw1[j] - cw0[j];
        float h      = ch1 - ch0;
        float invw   = __fdividef(1.0f, w);
        float delta  = h * invw;
        float t      = (xc[j] - cw0[j]) * invw;
        float tt     = t * t;
        float t1m    = t * (1.0f - t);

        float num    = h * fmaf(delta, tt, d0 * t1m);
        float den    = fmaf(d0 + d1 - 2.0f * delta, t1m, delta);
        float invden = __fdividef(1.0f, den);
        float y      = fmaf(num, invden, ch0);

        float omt = 1.0f - t;
        float dn  = (delta * delta) * (d1 * tt + 2.0f * delta * t1m + d0 * omt * omt);
        float ld  = __logf(dn * invden * invden);    // == log(dn) - 2 log(den)

        bool  inside = (xv[j] >= 0.0f) && (xv[j] <= 1.0f);
        float oy   = inside ? y  : xv[j];
        float old_ = inside ? ld : 0.0f;

        int r = r0 + j;
        if (!CHK || r < B) {
            out[r * DIM + d]         = oy;
            out[ldoff + r * DIM + d] = old_;
        }
    }
}

__global__ __launch_bounds__(256, 2)
void spline_kernel(const float* __restrict__ x, float* __restrict__ out, int B)
{
    extern __shared__ float s_tab[];
    {
        const float4* gs = (const float4*)g_tab;
        float4*       sd = (float4*)s_tab;
        #pragma unroll 4
        for (int i = threadIdx.x; i < TTOT / 4; i += 256) sd[i] = gs[i];
    }
    __syncthreads();

    const int d = threadIdx.x;                         // thread == dim
    const float* __restrict__ cw  = s_tab + d;         // [knot][dim], stride DIM
    const float* __restrict__ chh = s_tab + TPER + d;
    const float* __restrict__ dd  = s_tab + 2 * TPER + d;
    const int ldoff  = B * DIM;
    const int stride = gridDim.x * ROWS;

    for (int r0 = blockIdx.x * ROWS; r0 < B; r0 += stride) {
        if (r0 + ROWS <= B)
            process_rows<false>(x, out, cw, chh, dd, r0, B, ldoff, d);
        else
            process_rows<true >(x, out, cw, chh, dd, r0, B, ldoff, d);
    }
}

extern "C" void kernel_launch(void* const* d_in, const int* in_sizes, int n_in,
                              void* d_out, int out_size)
{
    const float* x      = (const float*)d_in[0];
    const float* width  = (const float*)d_in[1];
    const float* height = (const float*)d_in[2];
    const float* deriv  = (const float*)d_in[3];
    float*       out    = (float*)d_out;
    int B = in_sizes[0] / DIM;

    cudaFuncSetAttribute(spline_kernel,
                         cudaFuncAttributeMaxDynamicSharedMemorySize,
                         TTOT * (int)sizeof(float));

    precompute_kernel<<<32, 256>>>(width, height, deriv);
    spline_kernel<<<GRID_MAIN, 256, TTOT * sizeof(float)>>>(x, out, B);
}

// round 7
// speedup vs baseline: 1.3716x; 1.3716x over previous
#include <cuda_runtime.h>

#define DIM    256
#define BDIM   128                  // dims handled per block
#define NBINS  32
#define NKNOTS 33
#define TPER_G (NKNOTS * DIM)       // global table stride, layout [knot][256]
#define TTOT_G (3 * TPER_G)
#define TPER_S (NKNOTS * BDIM)      // smem table stride, layout [knot][128]
#define TTOT_S (3 * TPER_S)         // 12672 floats = 50688 B
#define ROWS   4
#define GRID_X 296                  // rows/iter per block = 2*ROWS = 8

// Precomputed knot tables, layout [knot][dim] (bank = dim mod 32 -> conflict-free
// for any data-dependent knot index):
// [0,TPER_G) cumwidths, [TPER_G,2*TPER_G) cumheights, [2*TPER_G,3*TPER_G) derivs.
__device__ float g_tab[TTOT_G];

__device__ __forceinline__ float softplus_f(float v) {
    return (v > 15.0f) ? v : log1pf(__expf(v));
}

// One warp per dim: softmax -> min-size floor -> inclusive scan -> knots.
__global__ void precompute_kernel(const float* __restrict__ width,
                                  const float* __restrict__ height,
                                  const float* __restrict__ deriv)
{
    int warp = (blockIdx.x * blockDim.x + threadIdx.x) >> 5;  // = dim
    int lane = threadIdx.x & 31;
    if (warp >= DIM) return;

    #pragma unroll
    for (int a = 0; a < 2; ++a) {
        const float* src = a ? height : width;
        float v = src[warp * NBINS + lane];

        float m = v;
        #pragma unroll
        for (int o = 16; o; o >>= 1) m = fmaxf(m, __shfl_xor_sync(0xffffffffu, m, o));
        float e = __expf(v - m);
        float s = e;
        #pragma unroll
        for (int o = 16; o; o >>= 1) s += __shfl_xor_sync(0xffffffffu, s, o);

        float size = 1e-3f + (1.0f - NBINS * 1e-3f) * (e / s);

        // inclusive warp scan (cumsum)
        float c = size;
        #pragma unroll
        for (int o = 1; o < 32; o <<= 1) {
            float n = __shfl_up_sync(0xffffffffu, c, o);
            if (lane >= o) c += n;
        }

        float* knots = g_tab + a * TPER_G;                         // [knot][dim]
        knots[(lane + 1) * DIM + warp] = (lane == 31) ? 1.0f : c;  // pin last to UPPER
        if (lane == 0) knots[warp] = 0.0f;                         // pin first to LOWER
    }

    {
        // derivatives: MIN_DERIVATIVE + softplus(pad(deriv, const));
        // boundary value: MIN_DERIVATIVE + softplus(log(expm1(1-MIN_DERIVATIVE))) = 1.0
        float* dd = g_tab + 2 * TPER_G;
        if (lane < NBINS - 1)
            dd[(lane + 1) * DIM + warp] = 1e-3f + softplus_f(deriv[warp * (NBINS - 1) + lane]);
        if (lane == 31) { dd[warp] = 1.0f; dd[NBINS * DIM + warp] = 1.0f; }
    }
}

template <bool CHK>
__device__ __forceinline__ void process_rows(
    const float* __restrict__ x, float* __restrict__ out, float* __restrict__ out2,
    const float* __restrict__ cw, const float* __restrict__ chh,
    const float* __restrict__ dd,
    int r0, int B, int d)
{
    float xv[ROWS], xc[ROWS];
    #pragma unroll
    for (int j = 0; j < ROWS; ++j) {
        int r = r0 + j;
        xv[j] = (!CHK || r < B) ? x[r * DIM + d] : 0.5f;
    }
    #pragma unroll
    for (int j = 0; j < ROWS; ++j)
        xc[j] = fminf(fmaxf(xv[j], 0.0f), 1.0f);

    // Arithmetic guess + exact fixup. Knots are near-uniform (softmax of small
    // logits), so the loops statistically never iterate, but remain correct for
    // arbitrary knot spacing. (c0, c1) carry the bracketing knot values; p walks
    // by +-BDIM so no index remultiplication happens inside the fixup.
    int   bin[ROWS];
    float cw0[ROWS], cw1[ROWS];
    #pragma unroll
    for (int j = 0; j < ROWS; ++j) {
        int g = min((int)(xc[j] * (float)NBINS), NBINS - 1);
        const float* p = cw + g * BDIM;
        float c0 = p[0];
        float c1 = p[BDIM];
        while (g > 0 && c0 > xc[j])          { --g; p -= BDIM; c1 = c0; c0 = p[0]; }
        while (g < NBINS - 1 && c1 <= xc[j]) { ++g; p += BDIM; c0 = c1; c1 = p[BDIM]; }
        bin[j] = g; cw0[j] = c0; cw1[j] = c1;
    }

    #pragma unroll
    for (int j = 0; j < ROWS; ++j) {
        int   b   = bin[j] * BDIM;
        float ch0 = chh[b], ch1 = chh[b + BDIM];
        float d0  = dd[b],  d1  = dd[b + BDIM];

        float w      = cw1[j] - cw0[j];
        float h      = ch1 - ch0;
        float invw   = __fdividef(1.0f, w);
        float delta  = h * invw;
        float t      = (xc[j] - cw0[j]) * invw;
        float tt     = t * t;
        float t1m    = t * (1.0f - t);

        float num    = h * fmaf(delta, tt, d0 * t1m);
        float den    = fmaf(d0 + d1 - 2.0f * delta, t1m, delta);
        float invden = __fdividef(1.0f, den);
        float y      = fmaf(num, invden, ch0);

        float omt = 1.0f - t;
        float dn  = (delta * delta) * (d1 * tt + 2.0f * delta * t1m + d0 * omt * omt);
        float ld  = __logf(dn * invden * invden);    // == log(dn) - 2 log(den)

        bool  inside = (xv[j] >= 0.0f) && (xv[j] <= 1.0f);
        float oy   = inside ? y  : xv[j];
        float old_ = inside ? ld : 0.0f;

        int r = r0 + j;
        if (!CHK || r < B) {
            out [r * DIM + d] = oy;
            out2[r * DIM + d] = old_;
        }
    }
}

__global__ __launch_bounds__(256, 4)
void spline_kernel(const float* __restrict__ x, float* __restrict__ out, int B)
{
    extern __shared__ float s_tab[];
    const int dbase = blockIdx.y * BDIM;   // which 128-dim half this block owns

    // Copy this block's dim-slice of the tables: s[tab][k][dl] = g[tab][k][dbase+dl]
    {
        // 3 tables x 33 knots x 128 dims; rows of 128 floats -> 32 float4 per row
        for (int i = threadIdx.x; i < 3 * NKNOTS * (BDIM / 4); i += 256) {
            int row = i >> 5;                 // which (tab,knot) row, 0..98
            int c4  = i & 31;                 // float4 index within row
            const float4* src = (const float4*)(g_tab + row * DIM + dbase);
            ((float4*)(s_tab + row * BDIM))[c4] = src[c4];
        }
    }
    __syncthreads();

    const int tid  = threadIdx.x;
    const int dl   = tid & (BDIM - 1);        // dim within slice
    const int rsub = tid >> 7;                // 0 or 1: row subgroup
    const int d    = dbase + dl;              // global dim

    const float* __restrict__ cw  = s_tab + dl;              // [knot][128]
    const float* __restrict__ chh = s_tab + TPER_S + dl;
    const float* __restrict__ dd  = s_tab + 2 * TPER_S + dl;
    float* __restrict__ out2 = out + (size_t)B * DIM;        // logdet plane
    const int stride = GRID_X * 2 * ROWS;

    for (int r0 = blockIdx.x * 2 * ROWS + rsub * ROWS; r0 < B; r0 += stride) {
        if (r0 + ROWS <= B)
            process_rows<false>(x, out, out2, cw, chh, dd, r0, B, d);
        else
            process_rows<true >(x, out, out2, cw, chh, dd, r0, B, d);
    }
}

extern "C" void kernel_launch(void* const* d_in, const int* in_sizes, int n_in,
                              void* d_out, int out_size)
{
    const float* x      = (const float*)d_in[0];
    const float* width  = (const float*)d_in[1];
    const float* height = (const float*)d_in[2];
    const float* deriv  = (const float*)d_in[3];
    float*       out    = (float*)d_out;
    int B = in_sizes[0] / DIM;

    cudaFuncSetAttribute(spline_kernel,
                         cudaFuncAttributeMaxDynamicSharedMemorySize,
                         TTOT_S * (int)sizeof(float));

    precompute_kernel<<<32, 256>>>(width, height, deriv);
    dim3 grid(GRID_X, DIM / BDIM);
    spline_kernel<<<grid, 256, TTOT_S * sizeof(float)>>>(x, out, B);
}

// round 13
// speedup vs baseline: 1.5726x; 1.1465x over previous
#include <cuda_runtime.h>

#define DIM    256
#define BDIM   64                   // dims handled per block
#define NBINS  32
#define NKNOTS 33
#define ROWS   4
#define GRID_X 222                  // 222 * 4 y-blocks = 888 = 148 SMs * 6 CTAs

// Global precomputed table, layout [knot][dim]:
//   g_knot[k*DIM + d] = {cumwidth, cumheight, derivative, pad}
__device__ float4 g_knot[NKNOTS * DIM];

#define SMEM_BYTES (NKNOTS * BDIM * (int)sizeof(float4))   // 33792 B per CTA

__device__ __forceinline__ float softplus_f(float v) {
    return (v > 15.0f) ? v : log1pf(__expf(v));
}

// One warp per dim: softmax -> min-size floor -> inclusive scan -> knots.
__global__ void precompute_kernel(const float* __restrict__ width,
                                  const float* __restrict__ height,
                                  const float* __restrict__ deriv)
{
    int warp = (blockIdx.x * blockDim.x + threadIdx.x) >> 5;  // = dim
    int lane = threadIdx.x & 31;
    if (warp >= DIM) return;

    #pragma unroll
    for (int a = 0; a < 2; ++a) {
        const float* src = a ? height : width;
        float v = src[warp * NBINS + lane];

        float m = v;
        #pragma unroll
        for (int o = 16; o; o >>= 1) m = fmaxf(m, __shfl_xor_sync(0xffffffffu, m, o));
        float e = __expf(v - m);
        float s = e;
        #pragma unroll
        for (int o = 16; o; o >>= 1) s += __shfl_xor_sync(0xffffffffu, s, o);

        float size = 1e-3f + (1.0f - NBINS * 1e-3f) * (e / s);

        // inclusive warp scan (cumsum)
        float c = size;
        #pragma unroll
        for (int o = 1; o < 32; o <<= 1) {
            float n = __shfl_up_sync(0xffffffffu, c, o);
            if (lane >= o) c += n;
        }

        float knot = (lane == 31) ? 1.0f : c;       // pin last to UPPER
        if (a == 0) {
            g_knot[(lane + 1) * DIM + warp].x = knot;
            if (lane == 0) g_knot[warp].x = 0.0f;   // pin first to LOWER
        } else {
            g_knot[(lane + 1) * DIM + warp].y = knot;
            if (lane == 0) g_knot[warp].y = 0.0f;
        }
    }

    {
        // derivatives: MIN_DERIVATIVE + softplus(pad(deriv, const));
        // boundary value: MIN_DERIVATIVE + softplus(log(expm1(1-MIN_DERIVATIVE))) = 1.0
        if (lane < NBINS - 1)
            g_knot[(lane + 1) * DIM + warp].z =
                1e-3f + softplus_f(deriv[warp * (NBINS - 1) + lane]);
        if (lane == 31) { g_knot[warp].z = 1.0f; g_knot[NBINS * DIM + warp].z = 1.0f; }
        g_knot[lane * DIM + warp].w = 0.0f;
        if (lane == 0) g_knot[NBINS * DIM + warp].w = 0.0f;
    }
}

template <bool CHK>
__device__ __forceinline__ void process_rows(
    const float* __restrict__ x, float* __restrict__ out, float* __restrict__ out2,
    const float4* __restrict__ tab,
    int r0, int B, int d)
{
    // front-batched loads: ROWS independent LDGs in flight
    float xv[ROWS];
    #pragma unroll
    for (int j = 0; j < ROWS; ++j) {
        int r = r0 + j;
        xv[j] = (!CHK || r < B) ? x[r * DIM + d] : 0.5f;
    }

    #pragma unroll
    for (int j = 0; j < ROWS; ++j) {
        float xc = fminf(fmaxf(xv[j], 0.0f), 1.0f);

        // Arithmetic guess + exact fixup. Knots are near-uniform (softmax of
        // small logits), so the loops statistically never iterate, but remain
        // correct for arbitrary spacing. Each probe fetches the full knot
        // record {cw, ch, d}, so at loop exit all six spline parameters are
        // already in registers - no further table access.
        // Bank check: word = g*256 + 4*dl -> each LDS.128 phase covers all 32
        // banks exactly once, independent of the data-dependent g.
        int g = min((int)(xc * (float)NBINS), NBINS - 1);
        const float4* p = tab + g * BDIM;
        float4 k0 = p[0];
        float4 k1 = p[BDIM];
        while (g > 0 && k0.x > xc)          { --g; p -= BDIM; k1 = k0; k0 = p[0]; }
        while (g < NBINS - 1 && k1.x <= xc) { ++g; p += BDIM; k0 = k1; k1 = p[BDIM]; }

        float w      = k1.x - k0.x;
        float h      = k1.y - k0.y;
        float d0     = k0.z;
        float d1     = k1.z;
        float invw   = __fdividef(1.0f, w);
        float delta  = h * invw;
        float t      = (xc - k0.x) * invw;
        float tt     = t * t;
        float t1m    = t * (1.0f - t);

        float num    = h * fmaf(delta, tt, d0 * t1m);
        float den    = fmaf(d0 + d1 - 2.0f * delta, t1m, delta);
        float invden = __fdividef(1.0f, den);
        float y      = fmaf(num, invden, k0.y);

        float omt = 1.0f - t;
        float dn  = (delta * delta) * (d1 * tt + 2.0f * delta * t1m + d0 * omt * omt);
        float ld  = __logf(dn * invden * invden);    // == log(dn) - 2 log(den)

        bool  inside = (xv[j] >= 0.0f) && (xv[j] <= 1.0f);
        float oy   = inside ? y  : xv[j];
        float old_ = inside ? ld : 0.0f;

        int r = r0 + j;
        if (!CHK || r < B) {
            out [r * DIM + d] = oy;
            out2[r * DIM + d] = old_;
        }
    }
}

__global__ __launch_bounds__(256, 6)
void spline_kernel(const float* __restrict__ x, float* __restrict__ out, int B)
{
    extern __shared__ float4 s_tab[];
    const int dbase = blockIdx.y * BDIM;   // which 64-dim slice this block owns

    // Copy this block's dim-slice: 33 knot rows x 64 float4.
    for (int i = threadIdx.x; i < NKNOTS * BDIM; i += 256) {
        int row = i >> 6;                  // knot
        int c   = i & (BDIM - 1);          // dim within slice
        s_tab[i] = g_knot[row * DIM + dbase + c];
    }
    __syncthreads();

    const int tid  = threadIdx.x;
    const int dl   = tid & (BDIM - 1);        // dim within slice
    const int rsub = tid >> 6;                // 0..3: row subgroup
    const int d    = dbase + dl;              // global dim

    const float4* __restrict__ tab = s_tab + dl;             // stride BDIM
    float* __restrict__ out2 = out + (size_t)B * DIM;        // logdet plane
    const int stride = gridDim.x * 4 * ROWS;

    for (int r0 = blockIdx.x * 4 * ROWS + rsub * ROWS; r0 < B; r0 += stride) {
        if (r0 + ROWS <= B)
            process_rows<false>(x, out, out2, tab, r0, B, d);
        else
            process_rows<true >(x, out, out2, tab, r0, B, d);
    }
}

extern "C" void kernel_launch(void* const* d_in, const int* in_sizes, int n_in,
                              void* d_out, int out_size)
{
    const float* x      = (const float*)d_in[0];
    const float* width  = (const float*)d_in[1];
    const float* height = (const float*)d_in[2];
    const float* deriv  = (const float*)d_in[3];
    float*       out    = (float*)d_out;
    int B = in_sizes[0] / DIM;

    cudaFuncSetAttribute(spline_kernel,
                         cudaFuncAttributeMaxDynamicSharedMemorySize,
                         SMEM_BYTES);

    precompute_kernel<<<32, 256>>>(width, height, deriv);
    dim3 grid(GRID_X, DIM / BDIM);
    spline_kernel<<<grid, 256, SMEM_BYTES>>>(x, out, B);
}